// round 12
// baseline (speedup 1.0000x reference)
#include <cuda_runtime.h>
#include <cuda_bf16.h>
#include <mma.h>
#include <math.h>

using namespace nvcuda;

#define NUM_USERS 100000
#define NUM_ITEMS 50000
#define N_NODES   150000
#define N_EDGES   2400000
#define EMB       64
#define BATCH     4096
#define TAU       0.2f
#define SSL_LAMBDA 0.1f
#define REG_LAMBDA 1e-4f

#define NVEC4      (N_NODES * EMB / 4)    // 2,400,000 == N_EDGES
#define NROWS_PAD  150016                 // 586 * 256
#define SCAN_BLKS  586
#define NLIST      (3 * BATCH)            // 12288 max needed rows

// ---------------- device scratch (static, zero-initialized at load) ----------
__device__ __align__(16) __nv_bfloat16 g_b0[N_NODES * EMB];
__device__ __align__(16) __nv_bfloat16 g_b1[N_NODES * EMB];
__device__ __align__(16) __nv_bfloat16 g_b2[N_NODES * EMB];
__device__ __align__(16) __nv_bfloat16 g_b3[N_NODES * EMB];
__device__ __align__(16) __nv_bfloat16 g_unb[BATCH * EMB];
__device__ __align__(16) __nv_bfloat16 g_pnb[BATCH * EMB];
__device__ float g_rowsum[BATCH];   // zeroed at end of k_logsum each run
__device__ float g_scal[4];         // zeroed at end of k_final each run
__device__ int   g_ctr;             // zeroed at end of k_final each run
__device__ int   g_need[N_NODES];   // flags; cleared by k_spmm_list each run
__device__ int   g_list[NLIST];
__device__ int   g_list_ctr;        // zeroed at end of k_final each run

// CSR scratch
__device__ int   g_deg[NROWS_PAD];  // zeroed inside k_gemm each run
__device__ int   g_rowptr[NROWS_PAD];
__device__ int   g_fill[NROWS_PAD];
__device__ __align__(8) int2 g_epack[N_EDGES];   // {col, bf16x2{v,v}}

// ---------------- combo: b0 = bf16(concat(uw,iw)), histogram, batch-mark -----
__global__ __launch_bounds__(256) void k_combo(const float* __restrict__ uw,
                                               const float* __restrict__ iw,
                                               const int*   __restrict__ rows,
                                               const int*   __restrict__ user,
                                               const int*   __restrict__ pos,
                                               const int*   __restrict__ neg) {
    int i = blockIdx.x * blockDim.x + threadIdx.x;
    if (i < NLIST) {
        int node;
        if (i < BATCH)            node = user[i];
        else if (i < 2 * BATCH)   node = NUM_USERS + pos[i - BATCH];
        else                      node = NUM_USERS + neg[i - 2 * BATCH];
        if (atomicExch(&g_need[node], 1) == 0) {
            int p = atomicAdd(&g_list_ctr, 1);
            g_list[p] = node;
        }
    }
    const int UV = NUM_USERS * EMB / 4;
    float4 v = (i < UV) ? ((const float4*)uw)[i] : ((const float4*)iw)[i - UV];
    __nv_bfloat162 lo = __floats2bfloat162_rn(v.x, v.y);
    __nv_bfloat162 hi = __floats2bfloat162_rn(v.z, v.w);
    uint2 pk;
    pk.x = *reinterpret_cast<unsigned*>(&lo);
    pk.y = *reinterpret_cast<unsigned*>(&hi);
    ((uint2*)g_b0)[i] = pk;
    atomicAdd(&g_deg[rows[i]], 1);
}

// ---------------- CSR offsets: block scan + atomic base ----------------------
__global__ __launch_bounds__(256) void k_csr() {
    int i = blockIdx.x * 256 + threadIdx.x;
    int v = g_deg[i];
    int lane = threadIdx.x & 31, wid = threadIdx.x >> 5;
    int x = v;
    #pragma unroll
    for (int o = 1; o < 32; o <<= 1) {
        int y = __shfl_up_sync(0xffffffffu, x, o);
        if (lane >= o) x += y;
    }
    __shared__ int wsum[8];
    __shared__ int base_sh;
    if (lane == 31) wsum[wid] = x;
    __syncthreads();
    if (threadIdx.x < 8) {
        int t = wsum[threadIdx.x];
        #pragma unroll
        for (int o = 1; o < 8; o <<= 1) {
            int y = __shfl_up_sync(0xffu, t, o);
            if (threadIdx.x >= o) t += y;
        }
        wsum[threadIdx.x] = t;
    }
    __syncthreads();
    int incl = x + (wid ? wsum[wid - 1] : 0);
    if (threadIdx.x == 255) base_sh = atomicAdd(&g_ctr, incl);
    __syncthreads();
    int start = base_sh + incl - v;
    g_rowptr[i] = start;
    g_fill[i]   = start;
}

// ---------------- scatter: 8 edges/thread, 8 overlapping atomic chains -------
__global__ __launch_bounds__(256) void k_scatter(const int*   __restrict__ rows,
                                                 const int*   __restrict__ cols,
                                                 const float* __restrict__ vals) {
    int t = blockIdx.x * blockDim.x + threadIdx.x;
    if (t >= N_EDGES / 8) return;
    int e = t * 8;
    int4   ra = *(const int4*)(rows + e);
    int4   rb = *(const int4*)(rows + e + 4);
    int4   ca = *(const int4*)(cols + e);
    int4   cb = *(const int4*)(cols + e + 4);
    float4 va = *(const float4*)(vals + e);
    float4 vb = *(const float4*)(vals + e + 4);
    int p0 = atomicAdd(&g_fill[ra.x], 1);
    int p1 = atomicAdd(&g_fill[ra.y], 1);
    int p2 = atomicAdd(&g_fill[ra.z], 1);
    int p3 = atomicAdd(&g_fill[ra.w], 1);
    int p4 = atomicAdd(&g_fill[rb.x], 1);
    int p5 = atomicAdd(&g_fill[rb.y], 1);
    int p6 = atomicAdd(&g_fill[rb.z], 1);
    int p7 = atomicAdd(&g_fill[rb.w], 1);
    __nv_bfloat162 v0 = __bfloat162bfloat162(__float2bfloat16(va.x));
    __nv_bfloat162 v1 = __bfloat162bfloat162(__float2bfloat16(va.y));
    __nv_bfloat162 v2 = __bfloat162bfloat162(__float2bfloat16(va.z));
    __nv_bfloat162 v3 = __bfloat162bfloat162(__float2bfloat16(va.w));
    __nv_bfloat162 v4 = __bfloat162bfloat162(__float2bfloat16(vb.x));
    __nv_bfloat162 v5 = __bfloat162bfloat162(__float2bfloat16(vb.y));
    __nv_bfloat162 v6 = __bfloat162bfloat162(__float2bfloat16(vb.z));
    __nv_bfloat162 v7 = __bfloat162bfloat162(__float2bfloat16(vb.w));
    g_epack[p0] = (int2){ca.x, *reinterpret_cast<int*>(&v0)};
    g_epack[p1] = (int2){ca.y, *reinterpret_cast<int*>(&v1)};
    g_epack[p2] = (int2){ca.z, *reinterpret_cast<int*>(&v2)};
    g_epack[p3] = (int2){ca.w, *reinterpret_cast<int*>(&v3)};
    g_epack[p4] = (int2){cb.x, *reinterpret_cast<int*>(&v4)};
    g_epack[p5] = (int2){cb.y, *reinterpret_cast<int*>(&v5)};
    g_epack[p6] = (int2){cb.z, *reinterpret_cast<int*>(&v6)};
    g_epack[p7] = (int2){cb.w, *reinterpret_cast<int*>(&v7)};
}

// ---------------- SpMM row body: half-warp per neighbor, HFMA2 ---------------
// ep loads software-pipelined one chunk ahead so gathers + next ep loads
// overlap; per-chunk chain drops from (ep_lat + gather_lat) to gather_lat.
__device__ __forceinline__ void spmm_row(int w, int half, int sub,
                                         const __nv_bfloat16* __restrict__ b_in,
                                         __nv_bfloat16*       __restrict__ b_out) {
    int start = g_rowptr[w];
    int deg   = g_deg[w];
    const int2* ep = g_epack + start;

    __nv_bfloat162 acc0 = __floats2bfloat162_rn(0.f, 0.f);
    __nv_bfloat162 acc1 = acc0;

    int nch = deg >> 3;
    int j = nch << 3;
    if (nch > 0) {
        int2 e0 = ep[0 + half];
        int2 e1 = ep[2 + half];
        int2 e2 = ep[4 + half];
        int2 e3 = ep[6 + half];
        for (int c = 1; c <= nch; c++) {
            // consume cols/vals from e-regs
            unsigned a0 = (unsigned)e0.x * EMB + sub * 4;
            unsigned a1 = (unsigned)e1.x * EMB + sub * 4;
            unsigned a2 = (unsigned)e2.x * EMB + sub * 4;
            unsigned a3 = (unsigned)e3.x * EMB + sub * 4;
            unsigned v0 = (unsigned)e0.y, v1 = (unsigned)e1.y;
            unsigned v2 = (unsigned)e2.y, v3 = (unsigned)e3.y;
            // issue 4 gathers
            uint2 r0 = *(const uint2*)(b_in + a0);
            uint2 r1 = *(const uint2*)(b_in + a1);
            uint2 r2 = *(const uint2*)(b_in + a2);
            uint2 r3 = *(const uint2*)(b_in + a3);
            // prefetch next chunk's edge records while gathers are in flight
            if (c < nch) {
                const int2* epn = ep + (c << 3);
                e0 = epn[0 + half];
                e1 = epn[2 + half];
                e2 = epn[4 + half];
                e3 = epn[6 + half];
            }
            __nv_bfloat162 bv0 = *reinterpret_cast<__nv_bfloat162*>(&v0);
            __nv_bfloat162 bv1 = *reinterpret_cast<__nv_bfloat162*>(&v1);
            __nv_bfloat162 bv2 = *reinterpret_cast<__nv_bfloat162*>(&v2);
            __nv_bfloat162 bv3 = *reinterpret_cast<__nv_bfloat162*>(&v3);
            acc0 = __hfma2(*reinterpret_cast<__nv_bfloat162*>(&r0.x), bv0, acc0);
            acc1 = __hfma2(*reinterpret_cast<__nv_bfloat162*>(&r0.y), bv0, acc1);
            acc0 = __hfma2(*reinterpret_cast<__nv_bfloat162*>(&r1.x), bv1, acc0);
            acc1 = __hfma2(*reinterpret_cast<__nv_bfloat162*>(&r1.y), bv1, acc1);
            acc0 = __hfma2(*reinterpret_cast<__nv_bfloat162*>(&r2.x), bv2, acc0);
            acc1 = __hfma2(*reinterpret_cast<__nv_bfloat162*>(&r2.y), bv2, acc1);
            acc0 = __hfma2(*reinterpret_cast<__nv_bfloat162*>(&r3.x), bv3, acc0);
            acc1 = __hfma2(*reinterpret_cast<__nv_bfloat162*>(&r3.y), bv3, acc1);
        }
    }
    for (; j < deg; j += 2) {
        int jj = j + half;
        if (jj < deg) {
            int2 e = ep[jj];
            uint2 r = *(const uint2*)(b_in + (unsigned)e.x * EMB + sub * 4);
            __nv_bfloat162 bv = *reinterpret_cast<__nv_bfloat162*>(&e.y);
            acc0 = __hfma2(*reinterpret_cast<__nv_bfloat162*>(&r.x), bv, acc0);
            acc1 = __hfma2(*reinterpret_cast<__nv_bfloat162*>(&r.y), bv, acc1);
        }
    }

    float2 f0 = __bfloat1622float2(acc0);
    float2 f1 = __bfloat1622float2(acc1);
    f0.x += __shfl_xor_sync(0xffffffffu, f0.x, 16);
    f0.y += __shfl_xor_sync(0xffffffffu, f0.y, 16);
    f1.x += __shfl_xor_sync(0xffffffffu, f1.x, 16);
    f1.y += __shfl_xor_sync(0xffffffffu, f1.y, 16);
    if (half == 0) {
        __nv_bfloat162 lo = __floats2bfloat162_rn(f0.x, f0.y);
        __nv_bfloat162 hi = __floats2bfloat162_rn(f1.x, f1.y);
        uint2 pk;
        pk.x = *reinterpret_cast<unsigned*>(&lo);
        pk.y = *reinterpret_cast<unsigned*>(&hi);
        *(uint2*)(b_out + (size_t)w * EMB + sub * 4) = pk;
    }
}

// full-table SpMM (layers 1, 2)
__global__ __launch_bounds__(256) void k_spmm(const __nv_bfloat16* __restrict__ b_in,
                                              __nv_bfloat16*       __restrict__ b_out) {
    int w = (blockIdx.x * 256 + threadIdx.x) >> 5;
    int lane = threadIdx.x & 31;
    if (w >= N_NODES) return;
    spmm_row(w, lane >> 4, lane & 15, b_in, b_out);
}

// list-restricted SpMM (layer 3); clears flags
__global__ __launch_bounds__(256) void k_spmm_list(const __nv_bfloat16* __restrict__ b_in,
                                                   __nv_bfloat16*       __restrict__ b_out) {
    int wi = (blockIdx.x * 256 + threadIdx.x) >> 5;
    int lane = threadIdx.x & 31;
    if (wi >= g_list_ctr) return;
    int w = g_list[wi];
    if (lane == 0) g_need[w] = 0;
    spmm_row(w, lane >> 4, lane & 15, b_in, b_out);
}

// ---------------- gather: fp32 e0 + bf16 layers; BPR/reg/diag; bf16 un/pn ----
__global__ __launch_bounds__(256) void k_gather(const int* __restrict__ user,
                                                const int* __restrict__ pos,
                                                const int* __restrict__ neg,
                                                const float* __restrict__ uw,
                                                const float* __restrict__ iw) {
    int gw   = (blockIdx.x * blockDim.x + threadIdx.x) >> 5;
    int lane = threadIdx.x & 31;
    if (gw >= BATCH) return;
    int ui = user[gw], pi = pos[gw], ni = neg[gw];
    size_t uoff = (size_t)ui * EMB + lane * 2;
    size_t poff = (size_t)pi * EMB + lane * 2;
    size_t noff = (size_t)ni * EMB + lane * 2;
    size_t uno  = (size_t)ui * EMB + lane * 2;
    size_t pno  = (size_t)(NUM_USERS + pi) * EMB + lane * 2;
    size_t nno  = (size_t)(NUM_USERS + ni) * EMB + lane * 2;

    #define B2F(tab, off) __bfloat1622float2(*(const __nv_bfloat162*)((tab) + (off)))
    #define SUMALL(f32p, f32off, boff, dst) { \
        float2 base = *(const float2*)((f32p) + (f32off)); \
        float2 a1 = B2F(g_b1, boff), a2 = B2F(g_b2, boff), a3 = B2F(g_b3, boff); \
        dst.x = 0.25f * (base.x + a1.x + a2.x + a3.x); \
        dst.y = 0.25f * (base.y + a1.y + a2.y + a3.y); }
    float2 u, p, n;
    SUMALL(uw, uoff, uno, u);
    SUMALL(iw, poff, pno, p);
    SUMALL(iw, noff, nno, n);
    #undef SUMALL
    #undef B2F

    float s_up = u.x * p.x + u.y * p.y;
    float s_un = u.x * n.x + u.y * n.y;
    float s_uu = u.x * u.x + u.y * u.y;
    float s_pp = p.x * p.x + p.y * p.y;
    float s_nn = n.x * n.x + n.y * n.y;
    #pragma unroll
    for (int o = 16; o; o >>= 1) {
        s_up += __shfl_xor_sync(0xffffffffu, s_up, o);
        s_un += __shfl_xor_sync(0xffffffffu, s_un, o);
        s_uu += __shfl_xor_sync(0xffffffffu, s_uu, o);
        s_pp += __shfl_xor_sync(0xffffffffu, s_pp, o);
        s_nn += __shfl_xor_sync(0xffffffffu, s_nn, o);
    }
    float iu = rsqrtf(s_uu);
    float ip = rsqrtf(s_pp);
    *(__nv_bfloat162*)(g_unb + (size_t)gw * EMB + lane * 2) = __floats2bfloat162_rn(u.x * iu, u.y * iu);
    *(__nv_bfloat162*)(g_pnb + (size_t)gw * EMB + lane * 2) = __floats2bfloat162_rn(p.x * ip, p.y * ip);
    if (lane == 0) {
        float d  = s_up - s_un;
        float sp = fmaxf(-d, 0.0f) + log1pf(expf(-fabsf(d)));  // softplus(-d)
        atomicAdd(&g_scal[0], sp);
        atomicAdd(&g_scal[1], s_uu + s_pp + s_nn);
        float diag = s_up * iu * ip * (1.0f / TAU);             // exact pos logit
        atomicAdd(&g_scal[2], -diag);
    }
}

// ---------------- WMMA bf16 GEMM: 64x256 per block (A reused 4x) -------------
#define LDT 80
__global__ __launch_bounds__(256) void k_gemm() {
    __shared__ __nv_bfloat16 Asm[64 * LDT];
    __shared__ __nv_bfloat16 Bsm[64 * LDT];
    __shared__ float         Csm[64 * 64];
    int bi  = blockIdx.y * 64;
    int bj0 = blockIdx.x * 256;
    int tid = threadIdx.x;

    // housekeeping: re-zero g_deg for the next run (first 586 of 1024 blocks)
    int bid = blockIdx.y * 16 + blockIdx.x;
    if (bid < SCAN_BLKS) g_deg[bid * 256 + tid] = 0;

    // load A tile once
    #pragma unroll
    for (int pass = 0; pass < 2; pass++) {
        int row = pass * 32 + (tid >> 3);
        int col = (tid & 7) * 8;
        *(uint4*)(Asm + row * LDT + col) = *(const uint4*)(g_unb + (size_t)(bi + row) * EMB + col);
    }

    int wid = tid >> 5;
    int frow = wid >> 1;
    int fcol0 = (wid & 1) * 2;
    const float invTau = 1.0f / TAU;
    int row = tid >> 2;
    int seg = (tid & 3) * 16;
    float s_tot = 0.0f;

    for (int st = 0; st < 4; st++) {
        int bj = bj0 + st * 64;
        __syncthreads();   // Bsm free (prev mma done), Csm free (prev exp done)
        #pragma unroll
        for (int pass = 0; pass < 2; pass++) {
            int r = pass * 32 + (tid >> 3);
            int c = (tid & 7) * 8;
            *(uint4*)(Bsm + r * LDT + c) = *(const uint4*)(g_pnb + (size_t)(bj + r) * EMB + c);
        }
        __syncthreads();

        wmma::fragment<wmma::accumulator, 16, 16, 16, float> acc0, acc1;
        wmma::fill_fragment(acc0, 0.0f);
        wmma::fill_fragment(acc1, 0.0f);
        #pragma unroll
        for (int kk = 0; kk < 64; kk += 16) {
            wmma::fragment<wmma::matrix_a, 16, 16, 16, __nv_bfloat16, wmma::row_major> af;
            wmma::fragment<wmma::matrix_b, 16, 16, 16, __nv_bfloat16, wmma::col_major> bf0, bf1;
            wmma::load_matrix_sync(af, Asm + frow * 16 * LDT + kk, LDT);
            wmma::load_matrix_sync(bf0, Bsm + (fcol0 + 0) * 16 * LDT + kk, LDT);
            wmma::load_matrix_sync(bf1, Bsm + (fcol0 + 1) * 16 * LDT + kk, LDT);
            wmma::mma_sync(acc0, af, bf0, acc0);
            wmma::mma_sync(acc1, af, bf1, acc1);
        }
        wmma::store_matrix_sync(Csm + frow * 16 * 64 + (fcol0 + 0) * 16, acc0, 64, wmma::mem_row_major);
        wmma::store_matrix_sync(Csm + frow * 16 * 64 + (fcol0 + 1) * 16, acc1, 64, wmma::mem_row_major);
        __syncthreads();

        const float* Crow = Csm + row * 64 + seg;
        #pragma unroll
        for (int q = 0; q < 16; q++) s_tot += __expf(Crow[q] * invTau);
    }

    s_tot += __shfl_xor_sync(0xffffffffu, s_tot, 1);
    s_tot += __shfl_xor_sync(0xffffffffu, s_tot, 2);
    if ((tid & 3) == 0) atomicAdd(&g_rowsum[bi + row], s_tot);
}

// ---------------- sum of log(rowsum); zero rowsum for next run ---------------
__global__ __launch_bounds__(256) void k_logsum() {
    int i = blockIdx.x * blockDim.x + threadIdx.x;
    float v = logf(g_rowsum[i]);
    g_rowsum[i] = 0.0f;
    #pragma unroll
    for (int o = 16; o; o >>= 1) v += __shfl_xor_sync(0xffffffffu, v, o);
    __shared__ float ws[8];
    int lane = threadIdx.x & 31, wid = threadIdx.x >> 5;
    if (lane == 0) ws[wid] = v;
    __syncthreads();
    if (threadIdx.x == 0) {
        float s = 0.f;
        #pragma unroll
        for (int k = 0; k < 8; k++) s += ws[k];
        atomicAdd(&g_scal[2], s);
    }
}

// ---------------- finalize; reset accumulators for next run ------------------
__global__ void k_final(float* out) {
    float bpr = g_scal[0] / BATCH;
    float reg = 0.5f * g_scal[1] / BATCH * REG_LAMBDA;
    float na  = g_scal[2] / BATCH * SSL_LAMBDA;
    out[0] = bpr + reg + na;
    g_scal[0] = 0.f; g_scal[1] = 0.f; g_scal[2] = 0.f; g_scal[3] = 0.f;
    g_ctr = 0;
    g_list_ctr = 0;
}

// ---------------- host -------------------------------------------------------
extern "C" void kernel_launch(void* const* d_in, const int* in_sizes, int n_in,
                              void* d_out, int out_size) {
    const int*   user  = (const int*)d_in[0];
    const int*   pos   = (const int*)d_in[1];
    const int*   neg   = (const int*)d_in[2];
    const int*   arow  = (const int*)d_in[3];
    const int*   acol  = (const int*)d_in[4];
    const float* aval  = (const float*)d_in[5];
    const float* uw    = (const float*)d_in[6];
    const float* iw    = (const float*)d_in[7];
    float* out = (float*)d_out;

    __nv_bfloat16 *b0, *b1, *b2, *b3;
    cudaGetSymbolAddress((void**)&b0, g_b0);
    cudaGetSymbolAddress((void**)&b1, g_b1);
    cudaGetSymbolAddress((void**)&b2, g_b2);
    cudaGetSymbolAddress((void**)&b3, g_b3);

    const int TB = 256;
    const int edge_blocks  = N_EDGES / TB;                   // 9375
    const int scat_blocks  = (N_EDGES / 8 + TB - 1) / TB;    // 1172
    const int row_blocks   = (N_NODES * 32 + TB - 1) / TB;   // 18750
    const int list_blocks  = (NLIST * 32) / TB;              // 1536

    k_combo<<<edge_blocks, TB>>>(uw, iw, arow, user, pos, neg);    // 1
    k_csr<<<SCAN_BLKS, TB>>>();                              // 2
    k_scatter<<<scat_blocks, TB>>>(arow, acol, aval);        // 3
    k_spmm<<<row_blocks, TB>>>(b0, b1);                      // 4
    k_spmm<<<row_blocks, TB>>>(b1, b2);                      // 5
    k_spmm_list<<<list_blocks, TB>>>(b2, b3);                // 6
    k_gather<<<(BATCH * 32) / TB, TB>>>(user, pos, neg, uw, iw);   // 7
    k_gemm<<<dim3(16, 64), TB>>>();                          // 8
    k_logsum<<<BATCH / TB, TB>>>();                          // 9
    k_final<<<1, 1>>>(out);                                  // 10
}

// round 13
// speedup vs baseline: 1.1001x; 1.1001x over previous
#include <cuda_runtime.h>
#include <cuda_bf16.h>
#include <mma.h>
#include <math.h>

using namespace nvcuda;

#define NUM_USERS 100000
#define NUM_ITEMS 50000
#define N_NODES   150000
#define N_EDGES   2400000
#define EMB       64
#define BATCH     4096
#define TAU       0.2f
#define SSL_LAMBDA 0.1f
#define REG_LAMBDA 1e-4f

#define NVEC4      (N_NODES * EMB / 4)    // 2,400,000 == N_EDGES
#define NROWS_PAD  150016                 // 586 * 256
#define SCAN_BLKS  586
#define NLIST      (3 * BATCH)            // 12288 max needed rows

// ---------------- device scratch (static, zero-initialized at load) ----------
__device__ __align__(16) __nv_bfloat16 g_b0[N_NODES * EMB];
__device__ __align__(16) __nv_bfloat16 g_b1[N_NODES * EMB];
__device__ __align__(16) __nv_bfloat16 g_b2[N_NODES * EMB];
__device__ __align__(16) __nv_bfloat16 g_b3[N_NODES * EMB];
__device__ __align__(16) __nv_bfloat16 g_unb[BATCH * EMB];
__device__ __align__(16) __nv_bfloat16 g_pnb[BATCH * EMB];
__device__ float g_rowsum[BATCH];   // zeroed at end of k_logsum each run
__device__ float g_scal[4];         // zeroed at end of k_final each run
__device__ int   g_ctr;             // zeroed at end of k_final each run
__device__ int   g_need[N_NODES];   // flags; cleared by k_spmm_list each run
__device__ int   g_list[NLIST];
__device__ int   g_list_ctr;        // zeroed at end of k_final each run

// CSR scratch
__device__ int   g_deg[NROWS_PAD];  // zeroed inside k_gemm each run
__device__ int   g_rowptr[NROWS_PAD];
__device__ int   g_fill[NROWS_PAD];
__device__ __align__(8) int2 g_epack[N_EDGES];   // {col, bf16x2{v,v}}

// ---------------- combo: b0 = bf16(concat(uw,iw)), histogram, batch-mark -----
__global__ __launch_bounds__(256) void k_combo(const float* __restrict__ uw,
                                               const float* __restrict__ iw,
                                               const int*   __restrict__ rows,
                                               const int*   __restrict__ user,
                                               const int*   __restrict__ pos,
                                               const int*   __restrict__ neg) {
    int i = blockIdx.x * blockDim.x + threadIdx.x;
    if (i < NLIST) {
        int node;
        if (i < BATCH)            node = user[i];
        else if (i < 2 * BATCH)   node = NUM_USERS + pos[i - BATCH];
        else                      node = NUM_USERS + neg[i - 2 * BATCH];
        if (atomicExch(&g_need[node], 1) == 0) {
            int p = atomicAdd(&g_list_ctr, 1);
            g_list[p] = node;
        }
    }
    const int UV = NUM_USERS * EMB / 4;
    float4 v = (i < UV) ? ((const float4*)uw)[i] : ((const float4*)iw)[i - UV];
    __nv_bfloat162 lo = __floats2bfloat162_rn(v.x, v.y);
    __nv_bfloat162 hi = __floats2bfloat162_rn(v.z, v.w);
    uint2 pk;
    pk.x = *reinterpret_cast<unsigned*>(&lo);
    pk.y = *reinterpret_cast<unsigned*>(&hi);
    ((uint2*)g_b0)[i] = pk;
    atomicAdd(&g_deg[rows[i]], 1);
}

// ---------------- CSR offsets: block scan + atomic base ----------------------
__global__ __launch_bounds__(256) void k_csr() {
    int i = blockIdx.x * 256 + threadIdx.x;
    int v = g_deg[i];
    int lane = threadIdx.x & 31, wid = threadIdx.x >> 5;
    int x = v;
    #pragma unroll
    for (int o = 1; o < 32; o <<= 1) {
        int y = __shfl_up_sync(0xffffffffu, x, o);
        if (lane >= o) x += y;
    }
    __shared__ int wsum[8];
    __shared__ int base_sh;
    if (lane == 31) wsum[wid] = x;
    __syncthreads();
    if (threadIdx.x < 8) {
        int t = wsum[threadIdx.x];
        #pragma unroll
        for (int o = 1; o < 8; o <<= 1) {
            int y = __shfl_up_sync(0xffu, t, o);
            if (threadIdx.x >= o) t += y;
        }
        wsum[threadIdx.x] = t;
    }
    __syncthreads();
    int incl = x + (wid ? wsum[wid - 1] : 0);
    if (threadIdx.x == 255) base_sh = atomicAdd(&g_ctr, incl);
    __syncthreads();
    int start = base_sh + incl - v;
    g_rowptr[i] = start;
    g_fill[i]   = start;
}

// ---------------- scatter: 8 edges/thread, 8 overlapping atomic chains -------
__global__ __launch_bounds__(256) void k_scatter(const int*   __restrict__ rows,
                                                 const int*   __restrict__ cols,
                                                 const float* __restrict__ vals) {
    int t = blockIdx.x * blockDim.x + threadIdx.x;
    if (t >= N_EDGES / 8) return;
    int e = t * 8;
    int4   ra = *(const int4*)(rows + e);
    int4   rb = *(const int4*)(rows + e + 4);
    int4   ca = *(const int4*)(cols + e);
    int4   cb = *(const int4*)(cols + e + 4);
    float4 va = *(const float4*)(vals + e);
    float4 vb = *(const float4*)(vals + e + 4);
    int p0 = atomicAdd(&g_fill[ra.x], 1);
    int p1 = atomicAdd(&g_fill[ra.y], 1);
    int p2 = atomicAdd(&g_fill[ra.z], 1);
    int p3 = atomicAdd(&g_fill[ra.w], 1);
    int p4 = atomicAdd(&g_fill[rb.x], 1);
    int p5 = atomicAdd(&g_fill[rb.y], 1);
    int p6 = atomicAdd(&g_fill[rb.z], 1);
    int p7 = atomicAdd(&g_fill[rb.w], 1);
    __nv_bfloat162 v0 = __bfloat162bfloat162(__float2bfloat16(va.x));
    __nv_bfloat162 v1 = __bfloat162bfloat162(__float2bfloat16(va.y));
    __nv_bfloat162 v2 = __bfloat162bfloat162(__float2bfloat16(va.z));
    __nv_bfloat162 v3 = __bfloat162bfloat162(__float2bfloat16(va.w));
    __nv_bfloat162 v4 = __bfloat162bfloat162(__float2bfloat16(vb.x));
    __nv_bfloat162 v5 = __bfloat162bfloat162(__float2bfloat16(vb.y));
    __nv_bfloat162 v6 = __bfloat162bfloat162(__float2bfloat16(vb.z));
    __nv_bfloat162 v7 = __bfloat162bfloat162(__float2bfloat16(vb.w));
    g_epack[p0] = (int2){ca.x, *reinterpret_cast<int*>(&v0)};
    g_epack[p1] = (int2){ca.y, *reinterpret_cast<int*>(&v1)};
    g_epack[p2] = (int2){ca.z, *reinterpret_cast<int*>(&v2)};
    g_epack[p3] = (int2){ca.w, *reinterpret_cast<int*>(&v3)};
    g_epack[p4] = (int2){cb.x, *reinterpret_cast<int*>(&v4)};
    g_epack[p5] = (int2){cb.y, *reinterpret_cast<int*>(&v5)};
    g_epack[p6] = (int2){cb.z, *reinterpret_cast<int*>(&v6)};
    g_epack[p7] = (int2){cb.w, *reinterpret_cast<int*>(&v7)};
}

// ---------------- SpMM row body: half-warp per neighbor, HFMA2, MLP=4 --------
// (round-11 proven body: regs 32, occ ~80%, 46.9us/layer)
__device__ __forceinline__ void spmm_row(int w, int half, int sub,
                                         const __nv_bfloat16* __restrict__ b_in,
                                         __nv_bfloat16*       __restrict__ b_out) {
    int start = g_rowptr[w];
    int deg   = g_deg[w];
    const int2* ep = g_epack + start;

    __nv_bfloat162 acc0 = __floats2bfloat162_rn(0.f, 0.f);
    __nv_bfloat162 acc1 = acc0;

    #define DOE(E, R) { \
        __nv_bfloat162 v2 = *reinterpret_cast<const __nv_bfloat162*>(&(E).y); \
        acc0 = __hfma2(*reinterpret_cast<__nv_bfloat162*>(&(R).x), v2, acc0); \
        acc1 = __hfma2(*reinterpret_cast<__nv_bfloat162*>(&(R).y), v2, acc1); }

    int j = 0;
    for (; j + 8 <= deg; j += 8) {
        int2 e0 = ep[j + 0 + half];
        int2 e1 = ep[j + 2 + half];
        int2 e2 = ep[j + 4 + half];
        int2 e3 = ep[j + 6 + half];
        uint2 r0 = *(const uint2*)(b_in + (unsigned)e0.x * EMB + sub * 4);
        uint2 r1 = *(const uint2*)(b_in + (unsigned)e1.x * EMB + sub * 4);
        uint2 r2 = *(const uint2*)(b_in + (unsigned)e2.x * EMB + sub * 4);
        uint2 r3 = *(const uint2*)(b_in + (unsigned)e3.x * EMB + sub * 4);
        DOE(e0, r0);
        DOE(e1, r1);
        DOE(e2, r2);
        DOE(e3, r3);
    }
    for (; j < deg; j += 2) {
        int jj = j + half;
        if (jj < deg) {
            int2 e = ep[jj];
            uint2 r = *(const uint2*)(b_in + (unsigned)e.x * EMB + sub * 4);
            DOE(e, r);
        }
    }
    #undef DOE

    float2 f0 = __bfloat1622float2(acc0);
    float2 f1 = __bfloat1622float2(acc1);
    f0.x += __shfl_xor_sync(0xffffffffu, f0.x, 16);
    f0.y += __shfl_xor_sync(0xffffffffu, f0.y, 16);
    f1.x += __shfl_xor_sync(0xffffffffu, f1.x, 16);
    f1.y += __shfl_xor_sync(0xffffffffu, f1.y, 16);
    if (half == 0) {
        __nv_bfloat162 lo = __floats2bfloat162_rn(f0.x, f0.y);
        __nv_bfloat162 hi = __floats2bfloat162_rn(f1.x, f1.y);
        uint2 pk;
        pk.x = *reinterpret_cast<unsigned*>(&lo);
        pk.y = *reinterpret_cast<unsigned*>(&hi);
        *(uint2*)(b_out + (size_t)w * EMB + sub * 4) = pk;
    }
}

// full-table SpMM (layers 1, 2)
__global__ __launch_bounds__(256) void k_spmm(const __nv_bfloat16* __restrict__ b_in,
                                              __nv_bfloat16*       __restrict__ b_out) {
    int w = (blockIdx.x * 256 + threadIdx.x) >> 5;
    int lane = threadIdx.x & 31;
    if (w >= N_NODES) return;
    spmm_row(w, lane >> 4, lane & 15, b_in, b_out);
}

// list-restricted SpMM (layer 3); clears flags
__global__ __launch_bounds__(256) void k_spmm_list(const __nv_bfloat16* __restrict__ b_in,
                                                   __nv_bfloat16*       __restrict__ b_out) {
    int wi = (blockIdx.x * 256 + threadIdx.x) >> 5;
    int lane = threadIdx.x & 31;
    if (wi >= g_list_ctr) return;
    int w = g_list[wi];
    if (lane == 0) g_need[w] = 0;
    spmm_row(w, lane >> 4, lane & 15, b_in, b_out);
}

// ---------------- gather: fp32 e0 + bf16 layers; BPR/reg/diag; bf16 un/pn ----
__global__ __launch_bounds__(256) void k_gather(const int* __restrict__ user,
                                                const int* __restrict__ pos,
                                                const int* __restrict__ neg,
                                                const float* __restrict__ uw,
                                                const float* __restrict__ iw) {
    int gw   = (blockIdx.x * blockDim.x + threadIdx.x) >> 5;
    int lane = threadIdx.x & 31;
    if (gw >= BATCH) return;
    int ui = user[gw], pi = pos[gw], ni = neg[gw];
    size_t uoff = (size_t)ui * EMB + lane * 2;
    size_t poff = (size_t)pi * EMB + lane * 2;
    size_t noff = (size_t)ni * EMB + lane * 2;
    size_t uno  = (size_t)ui * EMB + lane * 2;
    size_t pno  = (size_t)(NUM_USERS + pi) * EMB + lane * 2;
    size_t nno  = (size_t)(NUM_USERS + ni) * EMB + lane * 2;

    #define B2F(tab, off) __bfloat1622float2(*(const __nv_bfloat162*)((tab) + (off)))
    #define SUMALL(f32p, f32off, boff, dst) { \
        float2 base = *(const float2*)((f32p) + (f32off)); \
        float2 a1 = B2F(g_b1, boff), a2 = B2F(g_b2, boff), a3 = B2F(g_b3, boff); \
        dst.x = 0.25f * (base.x + a1.x + a2.x + a3.x); \
        dst.y = 0.25f * (base.y + a1.y + a2.y + a3.y); }
    float2 u, p, n;
    SUMALL(uw, uoff, uno, u);
    SUMALL(iw, poff, pno, p);
    SUMALL(iw, noff, nno, n);
    #undef SUMALL
    #undef B2F

    float s_up = u.x * p.x + u.y * p.y;
    float s_un = u.x * n.x + u.y * n.y;
    float s_uu = u.x * u.x + u.y * u.y;
    float s_pp = p.x * p.x + p.y * p.y;
    float s_nn = n.x * n.x + n.y * n.y;
    #pragma unroll
    for (int o = 16; o; o >>= 1) {
        s_up += __shfl_xor_sync(0xffffffffu, s_up, o);
        s_un += __shfl_xor_sync(0xffffffffu, s_un, o);
        s_uu += __shfl_xor_sync(0xffffffffu, s_uu, o);
        s_pp += __shfl_xor_sync(0xffffffffu, s_pp, o);
        s_nn += __shfl_xor_sync(0xffffffffu, s_nn, o);
    }
    float iu = rsqrtf(s_uu);
    float ip = rsqrtf(s_pp);
    *(__nv_bfloat162*)(g_unb + (size_t)gw * EMB + lane * 2) = __floats2bfloat162_rn(u.x * iu, u.y * iu);
    *(__nv_bfloat162*)(g_pnb + (size_t)gw * EMB + lane * 2) = __floats2bfloat162_rn(p.x * ip, p.y * ip);
    if (lane == 0) {
        float d  = s_up - s_un;
        float sp = fmaxf(-d, 0.0f) + log1pf(expf(-fabsf(d)));  // softplus(-d)
        atomicAdd(&g_scal[0], sp);
        atomicAdd(&g_scal[1], s_uu + s_pp + s_nn);
        float diag = s_up * iu * ip * (1.0f / TAU);             // exact pos logit
        atomicAdd(&g_scal[2], -diag);
    }
}

// ---------------- WMMA bf16 GEMM: 64x256 per block (A reused 4x) -------------
#define LDT 80
__global__ __launch_bounds__(256) void k_gemm() {
    __shared__ __nv_bfloat16 Asm[64 * LDT];
    __shared__ __nv_bfloat16 Bsm[64 * LDT];
    __shared__ float         Csm[64 * 64];
    int bi  = blockIdx.y * 64;
    int bj0 = blockIdx.x * 256;
    int tid = threadIdx.x;

    // housekeeping: re-zero g_deg for the next run (first 586 of 1024 blocks)
    int bid = blockIdx.y * 16 + blockIdx.x;
    if (bid < SCAN_BLKS) g_deg[bid * 256 + tid] = 0;

    // load A tile once
    #pragma unroll
    for (int pass = 0; pass < 2; pass++) {
        int row = pass * 32 + (tid >> 3);
        int col = (tid & 7) * 8;
        *(uint4*)(Asm + row * LDT + col) = *(const uint4*)(g_unb + (size_t)(bi + row) * EMB + col);
    }

    int wid = tid >> 5;
    int frow = wid >> 1;
    int fcol0 = (wid & 1) * 2;
    const float invTau = 1.0f / TAU;
    int row = tid >> 2;
    int seg = (tid & 3) * 16;
    float s_tot = 0.0f;

    for (int st = 0; st < 4; st++) {
        int bj = bj0 + st * 64;
        __syncthreads();   // Bsm free (prev mma done), Csm free (prev exp done)
        #pragma unroll
        for (int pass = 0; pass < 2; pass++) {
            int r = pass * 32 + (tid >> 3);
            int c = (tid & 7) * 8;
            *(uint4*)(Bsm + r * LDT + c) = *(const uint4*)(g_pnb + (size_t)(bj + r) * EMB + c);
        }
        __syncthreads();

        wmma::fragment<wmma::accumulator, 16, 16, 16, float> acc0, acc1;
        wmma::fill_fragment(acc0, 0.0f);
        wmma::fill_fragment(acc1, 0.0f);
        #pragma unroll
        for (int kk = 0; kk < 64; kk += 16) {
            wmma::fragment<wmma::matrix_a, 16, 16, 16, __nv_bfloat16, wmma::row_major> af;
            wmma::fragment<wmma::matrix_b, 16, 16, 16, __nv_bfloat16, wmma::col_major> bf0, bf1;
            wmma::load_matrix_sync(af, Asm + frow * 16 * LDT + kk, LDT);
            wmma::load_matrix_sync(bf0, Bsm + (fcol0 + 0) * 16 * LDT + kk, LDT);
            wmma::load_matrix_sync(bf1, Bsm + (fcol0 + 1) * 16 * LDT + kk, LDT);
            wmma::mma_sync(acc0, af, bf0, acc0);
            wmma::mma_sync(acc1, af, bf1, acc1);
        }
        wmma::store_matrix_sync(Csm + frow * 16 * 64 + (fcol0 + 0) * 16, acc0, 64, wmma::mem_row_major);
        wmma::store_matrix_sync(Csm + frow * 16 * 64 + (fcol0 + 1) * 16, acc1, 64, wmma::mem_row_major);
        __syncthreads();

        const float* Crow = Csm + row * 64 + seg;
        #pragma unroll
        for (int q = 0; q < 16; q++) s_tot += __expf(Crow[q] * invTau);
    }

    s_tot += __shfl_xor_sync(0xffffffffu, s_tot, 1);
    s_tot += __shfl_xor_sync(0xffffffffu, s_tot, 2);
    if ((tid & 3) == 0) atomicAdd(&g_rowsum[bi + row], s_tot);
}

// ---------------- sum of log(rowsum); zero rowsum for next run ---------------
__global__ __launch_bounds__(256) void k_logsum() {
    int i = blockIdx.x * blockDim.x + threadIdx.x;
    float v = logf(g_rowsum[i]);
    g_rowsum[i] = 0.0f;
    #pragma unroll
    for (int o = 16; o; o >>= 1) v += __shfl_xor_sync(0xffffffffu, v, o);
    __shared__ float ws[8];
    int lane = threadIdx.x & 31, wid = threadIdx.x >> 5;
    if (lane == 0) ws[wid] = v;
    __syncthreads();
    if (threadIdx.x == 0) {
        float s = 0.f;
        #pragma unroll
        for (int k = 0; k < 8; k++) s += ws[k];
        atomicAdd(&g_scal[2], s);
    }
}

// ---------------- finalize; reset accumulators for next run ------------------
__global__ void k_final(float* out) {
    float bpr = g_scal[0] / BATCH;
    float reg = 0.5f * g_scal[1] / BATCH * REG_LAMBDA;
    float na  = g_scal[2] / BATCH * SSL_LAMBDA;
    out[0] = bpr + reg + na;
    g_scal[0] = 0.f; g_scal[1] = 0.f; g_scal[2] = 0.f; g_scal[3] = 0.f;
    g_ctr = 0;
    g_list_ctr = 0;
}

// ---------------- host -------------------------------------------------------
extern "C" void kernel_launch(void* const* d_in, const int* in_sizes, int n_in,
                              void* d_out, int out_size) {
    const int*   user  = (const int*)d_in[0];
    const int*   pos   = (const int*)d_in[1];
    const int*   neg   = (const int*)d_in[2];
    const int*   arow  = (const int*)d_in[3];
    const int*   acol  = (const int*)d_in[4];
    const float* aval  = (const float*)d_in[5];
    const float* uw    = (const float*)d_in[6];
    const float* iw    = (const float*)d_in[7];
    float* out = (float*)d_out;

    __nv_bfloat16 *b0, *b1, *b2, *b3;
    cudaGetSymbolAddress((void**)&b0, g_b0);
    cudaGetSymbolAddress((void**)&b1, g_b1);
    cudaGetSymbolAddress((void**)&b2, g_b2);
    cudaGetSymbolAddress((void**)&b3, g_b3);

    const int TB = 256;
    const int edge_blocks  = N_EDGES / TB;                   // 9375
    const int scat_blocks  = (N_EDGES / 8 + TB - 1) / TB;    // 1172
    const int row_blocks   = (N_NODES * 32 + TB - 1) / TB;   // 18750
    const int list_blocks  = (NLIST * 32) / TB;              // 1536

    k_combo<<<edge_blocks, TB>>>(uw, iw, arow, user, pos, neg);    // 1
    k_csr<<<SCAN_BLKS, TB>>>();                              // 2
    k_scatter<<<scat_blocks, TB>>>(arow, acol, aval);        // 3
    k_spmm<<<row_blocks, TB>>>(b0, b1);                      // 4
    k_spmm<<<row_blocks, TB>>>(b1, b2);                      // 5
    k_spmm_list<<<list_blocks, TB>>>(b2, b3);                // 6
    k_gather<<<(BATCH * 32) / TB, TB>>>(user, pos, neg, uw, iw);   // 7
    k_gemm<<<dim3(16, 64), TB>>>();                          // 8
    k_logsum<<<BATCH / TB, TB>>>();                          // 9
    k_final<<<1, 1>>>(out);                                  // 10
}

// round 14
// speedup vs baseline: 1.1226x; 1.0204x over previous
#include <cuda_runtime.h>
#include <cuda_bf16.h>
#include <mma.h>
#include <math.h>

using namespace nvcuda;

#define NUM_USERS 100000
#define NUM_ITEMS 50000
#define N_NODES   150000
#define N_EDGES   2400000
#define EMB       64
#define BATCH     4096
#define TAU       0.2f
#define SSL_LAMBDA 0.1f
#define REG_LAMBDA 1e-4f

#define NVEC4      (N_NODES * EMB / 4)    // 2,400,000 == N_EDGES
#define NROWS_PAD  150016                 // 586 * 256
#define SCAN_BLKS  586
#define NLIST      (3 * BATCH)            // 12288 max needed rows

// ---------------- device scratch (static, zero-initialized at load) ----------
__device__ __align__(16) __nv_bfloat16 g_b0[N_NODES * EMB];
__device__ __align__(16) __nv_bfloat16 g_b1[N_NODES * EMB];
__device__ __align__(16) __nv_bfloat16 g_b2[N_NODES * EMB];
__device__ __align__(16) __nv_bfloat16 g_b3[N_NODES * EMB];
__device__ __align__(16) __nv_bfloat16 g_unb[BATCH * EMB];
__device__ __align__(16) __nv_bfloat16 g_pnb[BATCH * EMB];
__device__ float g_rowsum[BATCH];   // zeroed at end of k_logsum each run
__device__ float g_scal[4];         // zeroed at end of k_final each run
__device__ int   g_ctr;             // zeroed at end of k_final each run
__device__ int   g_need[N_NODES];   // flags; cleared by k_spmm_list each run
__device__ int   g_list[NLIST];
__device__ int   g_list_ctr;        // zeroed at end of k_final each run

// CSR scratch
__device__ int   g_deg[NROWS_PAD];  // zeroed inside k_gemm each run
__device__ int   g_rowptr[NROWS_PAD];
__device__ int   g_rank[N_EDGES];   // intra-row rank of each edge (from histogram)
__device__ __align__(8) int2 g_epack[N_EDGES];   // {col, bf16x2{v,v}}

// ---------------- combo: b0 = bf16(concat(uw,iw)), histogram+rank, mark ------
__global__ __launch_bounds__(256) void k_combo(const float* __restrict__ uw,
                                               const float* __restrict__ iw,
                                               const int*   __restrict__ rows,
                                               const int*   __restrict__ user,
                                               const int*   __restrict__ pos,
                                               const int*   __restrict__ neg) {
    int i = blockIdx.x * blockDim.x + threadIdx.x;
    if (i < NLIST) {
        int node;
        if (i < BATCH)            node = user[i];
        else if (i < 2 * BATCH)   node = NUM_USERS + pos[i - BATCH];
        else                      node = NUM_USERS + neg[i - 2 * BATCH];
        if (atomicExch(&g_need[node], 1) == 0) {
            int p = atomicAdd(&g_list_ctr, 1);
            g_list[p] = node;
        }
    }
    const int UV = NUM_USERS * EMB / 4;
    float4 v = (i < UV) ? ((const float4*)uw)[i] : ((const float4*)iw)[i - UV];
    __nv_bfloat162 lo = __floats2bfloat162_rn(v.x, v.y);
    __nv_bfloat162 hi = __floats2bfloat162_rn(v.z, v.w);
    uint2 pk;
    pk.x = *reinterpret_cast<unsigned*>(&lo);
    pk.y = *reinterpret_cast<unsigned*>(&hi);
    ((uint2*)g_b0)[i] = pk;
    // histogram; the return value IS this edge's intra-row rank
    g_rank[i] = atomicAdd(&g_deg[rows[i]], 1);
}

// ---------------- CSR offsets: block scan + atomic base ----------------------
__global__ __launch_bounds__(256) void k_csr() {
    int i = blockIdx.x * 256 + threadIdx.x;
    int v = g_deg[i];
    int lane = threadIdx.x & 31, wid = threadIdx.x >> 5;
    int x = v;
    #pragma unroll
    for (int o = 1; o < 32; o <<= 1) {
        int y = __shfl_up_sync(0xffffffffu, x, o);
        if (lane >= o) x += y;
    }
    __shared__ int wsum[8];
    __shared__ int base_sh;
    if (lane == 31) wsum[wid] = x;
    __syncthreads();
    if (threadIdx.x < 8) {
        int t = wsum[threadIdx.x];
        #pragma unroll
        for (int o = 1; o < 8; o <<= 1) {
            int y = __shfl_up_sync(0xffu, t, o);
            if (threadIdx.x >= o) t += y;
        }
        wsum[threadIdx.x] = t;
    }
    __syncthreads();
    int incl = x + (wid ? wsum[wid - 1] : 0);
    if (threadIdx.x == 255) base_sh = atomicAdd(&g_ctr, incl);
    __syncthreads();
    g_rowptr[i] = base_sh + incl - v;
}

// ---------------- scatter: NO atomics — slot = rowptr[row] + rank ------------
__global__ __launch_bounds__(256) void k_scatter(const int*   __restrict__ rows,
                                                 const int*   __restrict__ cols,
                                                 const float* __restrict__ vals) {
    int t = blockIdx.x * blockDim.x + threadIdx.x;
    if (t >= N_EDGES / 4) return;
    int e = t * 4;
    int4   r4 = *(const int4*)(rows + e);
    int4   c4 = *(const int4*)(cols + e);
    float4 v4 = *(const float4*)(vals + e);
    int4   k4 = *(const int4*)(g_rank + e);
    // 4 independent gathered rowptr loads
    int p0 = g_rowptr[r4.x] + k4.x;
    int p1 = g_rowptr[r4.y] + k4.y;
    int p2 = g_rowptr[r4.z] + k4.z;
    int p3 = g_rowptr[r4.w] + k4.w;
    __nv_bfloat162 v0 = __bfloat162bfloat162(__float2bfloat16(v4.x));
    __nv_bfloat162 v1 = __bfloat162bfloat162(__float2bfloat16(v4.y));
    __nv_bfloat162 v2 = __bfloat162bfloat162(__float2bfloat16(v4.z));
    __nv_bfloat162 v3 = __bfloat162bfloat162(__float2bfloat16(v4.w));
    g_epack[p0] = (int2){c4.x, *reinterpret_cast<int*>(&v0)};
    g_epack[p1] = (int2){c4.y, *reinterpret_cast<int*>(&v1)};
    g_epack[p2] = (int2){c4.z, *reinterpret_cast<int*>(&v2)};
    g_epack[p3] = (int2){c4.w, *reinterpret_cast<int*>(&v3)};
}

// ---------------- SpMM row body: half-warp per neighbor, HFMA2, MLP=4 --------
// (round-11 proven body: regs 32, occ ~80%, 46.9us/layer)
__device__ __forceinline__ void spmm_row(int w, int half, int sub,
                                         const __nv_bfloat16* __restrict__ b_in,
                                         __nv_bfloat16*       __restrict__ b_out) {
    int start = g_rowptr[w];
    int deg   = g_deg[w];
    const int2* ep = g_epack + start;

    __nv_bfloat162 acc0 = __floats2bfloat162_rn(0.f, 0.f);
    __nv_bfloat162 acc1 = acc0;

    #define DOE(E, R) { \
        __nv_bfloat162 v2 = *reinterpret_cast<const __nv_bfloat162*>(&(E).y); \
        acc0 = __hfma2(*reinterpret_cast<__nv_bfloat162*>(&(R).x), v2, acc0); \
        acc1 = __hfma2(*reinterpret_cast<__nv_bfloat162*>(&(R).y), v2, acc1); }

    int j = 0;
    for (; j + 8 <= deg; j += 8) {
        int2 e0 = ep[j + 0 + half];
        int2 e1 = ep[j + 2 + half];
        int2 e2 = ep[j + 4 + half];
        int2 e3 = ep[j + 6 + half];
        uint2 r0 = *(const uint2*)(b_in + (unsigned)e0.x * EMB + sub * 4);
        uint2 r1 = *(const uint2*)(b_in + (unsigned)e1.x * EMB + sub * 4);
        uint2 r2 = *(const uint2*)(b_in + (unsigned)e2.x * EMB + sub * 4);
        uint2 r3 = *(const uint2*)(b_in + (unsigned)e3.x * EMB + sub * 4);
        DOE(e0, r0);
        DOE(e1, r1);
        DOE(e2, r2);
        DOE(e3, r3);
    }
    for (; j < deg; j += 2) {
        int jj = j + half;
        if (jj < deg) {
            int2 e = ep[jj];
            uint2 r = *(const uint2*)(b_in + (unsigned)e.x * EMB + sub * 4);
            DOE(e, r);
        }
    }
    #undef DOE

    float2 f0 = __bfloat1622float2(acc0);
    float2 f1 = __bfloat1622float2(acc1);
    f0.x += __shfl_xor_sync(0xffffffffu, f0.x, 16);
    f0.y += __shfl_xor_sync(0xffffffffu, f0.y, 16);
    f1.x += __shfl_xor_sync(0xffffffffu, f1.x, 16);
    f1.y += __shfl_xor_sync(0xffffffffu, f1.y, 16);
    if (half == 0) {
        __nv_bfloat162 lo = __floats2bfloat162_rn(f0.x, f0.y);
        __nv_bfloat162 hi = __floats2bfloat162_rn(f1.x, f1.y);
        uint2 pk;
        pk.x = *reinterpret_cast<unsigned*>(&lo);
        pk.y = *reinterpret_cast<unsigned*>(&hi);
        *(uint2*)(b_out + (size_t)w * EMB + sub * 4) = pk;
    }
}

// full-table SpMM (layers 1, 2)
__global__ __launch_bounds__(256) void k_spmm(const __nv_bfloat16* __restrict__ b_in,
                                              __nv_bfloat16*       __restrict__ b_out) {
    int w = (blockIdx.x * 256 + threadIdx.x) >> 5;
    int lane = threadIdx.x & 31;
    if (w >= N_NODES) return;
    spmm_row(w, lane >> 4, lane & 15, b_in, b_out);
}

// list-restricted SpMM (layer 3); clears flags
__global__ __launch_bounds__(256) void k_spmm_list(const __nv_bfloat16* __restrict__ b_in,
                                                   __nv_bfloat16*       __restrict__ b_out) {
    int wi = (blockIdx.x * 256 + threadIdx.x) >> 5;
    int lane = threadIdx.x & 31;
    if (wi >= g_list_ctr) return;
    int w = g_list[wi];
    if (lane == 0) g_need[w] = 0;
    spmm_row(w, lane >> 4, lane & 15, b_in, b_out);
}

// ---------------- gather: fp32 e0 + bf16 layers; BPR/reg/diag; bf16 un/pn ----
__global__ __launch_bounds__(256) void k_gather(const int* __restrict__ user,
                                                const int* __restrict__ pos,
                                                const int* __restrict__ neg,
                                                const float* __restrict__ uw,
                                                const float* __restrict__ iw) {
    int gw   = (blockIdx.x * blockDim.x + threadIdx.x) >> 5;
    int lane = threadIdx.x & 31;
    if (gw >= BATCH) return;
    int ui = user[gw], pi = pos[gw], ni = neg[gw];
    size_t uoff = (size_t)ui * EMB + lane * 2;
    size_t poff = (size_t)pi * EMB + lane * 2;
    size_t noff = (size_t)ni * EMB + lane * 2;
    size_t uno  = (size_t)ui * EMB + lane * 2;
    size_t pno  = (size_t)(NUM_USERS + pi) * EMB + lane * 2;
    size_t nno  = (size_t)(NUM_USERS + ni) * EMB + lane * 2;

    #define B2F(tab, off) __bfloat1622float2(*(const __nv_bfloat162*)((tab) + (off)))
    #define SUMALL(f32p, f32off, boff, dst) { \
        float2 base = *(const float2*)((f32p) + (f32off)); \
        float2 a1 = B2F(g_b1, boff), a2 = B2F(g_b2, boff), a3 = B2F(g_b3, boff); \
        dst.x = 0.25f * (base.x + a1.x + a2.x + a3.x); \
        dst.y = 0.25f * (base.y + a1.y + a2.y + a3.y); }
    float2 u, p, n;
    SUMALL(uw, uoff, uno, u);
    SUMALL(iw, poff, pno, p);
    SUMALL(iw, noff, nno, n);
    #undef SUMALL
    #undef B2F

    float s_up = u.x * p.x + u.y * p.y;
    float s_un = u.x * n.x + u.y * n.y;
    float s_uu = u.x * u.x + u.y * u.y;
    float s_pp = p.x * p.x + p.y * p.y;
    float s_nn = n.x * n.x + n.y * n.y;
    #pragma unroll
    for (int o = 16; o; o >>= 1) {
        s_up += __shfl_xor_sync(0xffffffffu, s_up, o);
        s_un += __shfl_xor_sync(0xffffffffu, s_un, o);
        s_uu += __shfl_xor_sync(0xffffffffu, s_uu, o);
        s_pp += __shfl_xor_sync(0xffffffffu, s_pp, o);
        s_nn += __shfl_xor_sync(0xffffffffu, s_nn, o);
    }
    float iu = rsqrtf(s_uu);
    float ip = rsqrtf(s_pp);
    *(__nv_bfloat162*)(g_unb + (size_t)gw * EMB + lane * 2) = __floats2bfloat162_rn(u.x * iu, u.y * iu);
    *(__nv_bfloat162*)(g_pnb + (size_t)gw * EMB + lane * 2) = __floats2bfloat162_rn(p.x * ip, p.y * ip);
    if (lane == 0) {
        float d  = s_up - s_un;
        float sp = fmaxf(-d, 0.0f) + log1pf(expf(-fabsf(d)));  // softplus(-d)
        atomicAdd(&g_scal[0], sp);
        atomicAdd(&g_scal[1], s_uu + s_pp + s_nn);
        float diag = s_up * iu * ip * (1.0f / TAU);             // exact pos logit
        atomicAdd(&g_scal[2], -diag);
    }
}

// ---------------- WMMA bf16 GEMM: 64x256 per block (A reused 4x) -------------
#define LDT 80
__global__ __launch_bounds__(256) void k_gemm() {
    __shared__ __nv_bfloat16 Asm[64 * LDT];
    __shared__ __nv_bfloat16 Bsm[64 * LDT];
    __shared__ float         Csm[64 * 64];
    int bi  = blockIdx.y * 64;
    int bj0 = blockIdx.x * 256;
    int tid = threadIdx.x;

    // housekeeping: re-zero g_deg for the next run (first 586 of 1024 blocks)
    int bid = blockIdx.y * 16 + blockIdx.x;
    if (bid < SCAN_BLKS) g_deg[bid * 256 + tid] = 0;

    // load A tile once
    #pragma unroll
    for (int pass = 0; pass < 2; pass++) {
        int row = pass * 32 + (tid >> 3);
        int col = (tid & 7) * 8;
        *(uint4*)(Asm + row * LDT + col) = *(const uint4*)(g_unb + (size_t)(bi + row) * EMB + col);
    }

    int wid = tid >> 5;
    int frow = wid >> 1;
    int fcol0 = (wid & 1) * 2;
    const float invTau = 1.0f / TAU;
    int row = tid >> 2;
    int seg = (tid & 3) * 16;
    float s_tot = 0.0f;

    for (int st = 0; st < 4; st++) {
        int bj = bj0 + st * 64;
        __syncthreads();
        #pragma unroll
        for (int pass = 0; pass < 2; pass++) {
            int r = pass * 32 + (tid >> 3);
            int c = (tid & 7) * 8;
            *(uint4*)(Bsm + r * LDT + c) = *(const uint4*)(g_pnb + (size_t)(bj + r) * EMB + c);
        }
        __syncthreads();

        wmma::fragment<wmma::accumulator, 16, 16, 16, float> acc0, acc1;
        wmma::fill_fragment(acc0, 0.0f);
        wmma::fill_fragment(acc1, 0.0f);
        #pragma unroll
        for (int kk = 0; kk < 64; kk += 16) {
            wmma::fragment<wmma::matrix_a, 16, 16, 16, __nv_bfloat16, wmma::row_major> af;
            wmma::fragment<wmma::matrix_b, 16, 16, 16, __nv_bfloat16, wmma::col_major> bf0, bf1;
            wmma::load_matrix_sync(af, Asm + frow * 16 * LDT + kk, LDT);
            wmma::load_matrix_sync(bf0, Bsm + (fcol0 + 0) * 16 * LDT + kk, LDT);
            wmma::load_matrix_sync(bf1, Bsm + (fcol0 + 1) * 16 * LDT + kk, LDT);
            wmma::mma_sync(acc0, af, bf0, acc0);
            wmma::mma_sync(acc1, af, bf1, acc1);
        }
        wmma::store_matrix_sync(Csm + frow * 16 * 64 + (fcol0 + 0) * 16, acc0, 64, wmma::mem_row_major);
        wmma::store_matrix_sync(Csm + frow * 16 * 64 + (fcol0 + 1) * 16, acc1, 64, wmma::mem_row_major);
        __syncthreads();

        const float* Crow = Csm + row * 64 + seg;
        #pragma unroll
        for (int q = 0; q < 16; q++) s_tot += __expf(Crow[q] * invTau);
    }

    s_tot += __shfl_xor_sync(0xffffffffu, s_tot, 1);
    s_tot += __shfl_xor_sync(0xffffffffu, s_tot, 2);
    if ((tid & 3) == 0) atomicAdd(&g_rowsum[bi + row], s_tot);
}

// ---------------- sum of log(rowsum); zero rowsum for next run ---------------
__global__ __launch_bounds__(256) void k_logsum() {
    int i = blockIdx.x * blockDim.x + threadIdx.x;
    float v = logf(g_rowsum[i]);
    g_rowsum[i] = 0.0f;
    #pragma unroll
    for (int o = 16; o; o >>= 1) v += __shfl_xor_sync(0xffffffffu, v, o);
    __shared__ float ws[8];
    int lane = threadIdx.x & 31, wid = threadIdx.x >> 5;
    if (lane == 0) ws[wid] = v;
    __syncthreads();
    if (threadIdx.x == 0) {
        float s = 0.f;
        #pragma unroll
        for (int k = 0; k < 8; k++) s += ws[k];
        atomicAdd(&g_scal[2], s);
    }
}

// ---------------- finalize; reset accumulators for next run ------------------
__global__ void k_final(float* out) {
    float bpr = g_scal[0] / BATCH;
    float reg = 0.5f * g_scal[1] / BATCH * REG_LAMBDA;
    float na  = g_scal[2] / BATCH * SSL_LAMBDA;
    out[0] = bpr + reg + na;
    g_scal[0] = 0.f; g_scal[1] = 0.f; g_scal[2] = 0.f; g_scal[3] = 0.f;
    g_ctr = 0;
    g_list_ctr = 0;
}

// ---------------- host -------------------------------------------------------
extern "C" void kernel_launch(void* const* d_in, const int* in_sizes, int n_in,
                              void* d_out, int out_size) {
    const int*   user  = (const int*)d_in[0];
    const int*   pos   = (const int*)d_in[1];
    const int*   neg   = (const int*)d_in[2];
    const int*   arow  = (const int*)d_in[3];
    const int*   acol  = (const int*)d_in[4];
    const float* aval  = (const float*)d_in[5];
    const float* uw    = (const float*)d_in[6];
    const float* iw    = (const float*)d_in[7];
    float* out = (float*)d_out;

    __nv_bfloat16 *b0, *b1, *b2, *b3;
    cudaGetSymbolAddress((void**)&b0, g_b0);
    cudaGetSymbolAddress((void**)&b1, g_b1);
    cudaGetSymbolAddress((void**)&b2, g_b2);
    cudaGetSymbolAddress((void**)&b3, g_b3);

    const int TB = 256;
    const int edge_blocks  = N_EDGES / TB;                   // 9375
    const int scat_blocks  = (N_EDGES / 4 + TB - 1) / TB;    // 2344
    const int row_blocks   = (N_NODES * 32 + TB - 1) / TB;   // 18750
    const int list_blocks  = (NLIST * 32) / TB;              // 1536

    k_combo<<<edge_blocks, TB>>>(uw, iw, arow, user, pos, neg);    // 1
    k_csr<<<SCAN_BLKS, TB>>>();                              // 2
    k_scatter<<<scat_blocks, TB>>>(arow, acol, aval);        // 3
    k_spmm<<<row_blocks, TB>>>(b0, b1);                      // 4
    k_spmm<<<row_blocks, TB>>>(b1, b2);                      // 5
    k_spmm_list<<<list_blocks, TB>>>(b2, b3);                // 6
    k_gather<<<(BATCH * 32) / TB, TB>>>(user, pos, neg, uw, iw);   // 7
    k_gemm<<<dim3(16, 64), TB>>>();                          // 8
    k_logsum<<<BATCH / TB, TB>>>();                          // 9
    k_final<<<1, 1>>>(out);                                  // 10
}